// round 4
// baseline (speedup 1.0000x reference)
#include <cuda_runtime.h>
#include <cuda_bf16.h>
#include <math.h>

#define NN 100000
#define EE 1600000
#define FIN 64
#define HID 16
#define CC 40

// ---------------- scratch (static device globals; no allocation) ----------------
__device__ float d_deg[NN];
__device__ float d_dinv[NN];
__device__ float d_norm[EE];
__device__ float d_z0[NN * HID];    // x @ W1[0]
__device__ float d_y1[NN * HID];    // x @ W1[1]   (projected BEFORE propagation)
__device__ float d_agg1[NN * HID];  // segsum(norm * y1[src])
__device__ float d_h[NN * HID];     // relu(z0 + agg1 + b1)
__device__ float d_agg2[NN * HID];  // segsum(norm * h[src])

// Host-side resolved device pointers (filled in prewarm ctor, pre-checkpoint).
static float* p_deg;
static float* p_dinv;
static float* p_norm;
static float* p_z0;
static float* p_y1;
static float* p_agg1;
static float* p_h;
static float* p_agg2;

// ---------------- kernels (explicit pointers; explicit n for prewarm) ---------
__global__ void k_zero(float* deg, float* agg1, float* agg2, int n) {
    int i = blockIdx.x * blockDim.x + threadIdx.x;
    if (i >= n) return;
    if (i < NN) deg[i] = 0.0f;
    agg1[i] = 0.0f;
    agg2[i] = 0.0f;
}

__global__ void k_deg(const int* __restrict__ ei, const float* __restrict__ w,
                      float* deg, int n) {
    int e = blockIdx.x * blockDim.x + threadIdx.x;
    if (e >= n) return;
    atomicAdd(&deg[ei[EE + e]], w[e]);   // dst = row 1
}

__global__ void k_dinv(const float* __restrict__ deg, float* dinv, int n) {
    int i = blockIdx.x * blockDim.x + threadIdx.x;
    if (i >= n) return;
    float dg = deg[i];
    dinv[i] = (dg > 0.0f) ? rsqrtf(dg) : 0.0f;
}

__global__ void k_norm(const int* __restrict__ ei, const float* __restrict__ w,
                       const float* __restrict__ dinv, float* nrm, int n) {
    int e = blockIdx.x * blockDim.x + threadIdx.x;
    if (e >= n) return;
    int s = ei[e], d = ei[EE + e];
    // lambda_max = 2 => norm = -dinv[src]*w*dinv[dst]
    nrm[e] = -dinv[s] * w[e] * dinv[d];
}

// z0 = x@W1[0], y1 = x@W1[1], fused (reads x once)
__global__ void __launch_bounds__(128, 1)
k_gemm1(const float* __restrict__ x, const float* __restrict__ W1,
        float* z0g, float* y1g, int n) {
    __shared__ float W0s[FIN * HID];
    __shared__ float W1s[FIN * HID];
    for (int i = threadIdx.x; i < FIN * HID; i += blockDim.x) {
        W0s[i] = W1[i];
        W1s[i] = W1[FIN * HID + i];
    }
    __syncthreads();
    int nd = blockIdx.x * blockDim.x + threadIdx.x;
    if (nd >= n) return;

    float acc0[HID], acc1[HID];
#pragma unroll
    for (int h = 0; h < HID; h++) { acc0[h] = 0.0f; acc1[h] = 0.0f; }

    const float4* xr = reinterpret_cast<const float4*>(x + (size_t)nd * FIN);
#pragma unroll
    for (int k4 = 0; k4 < FIN / 4; k4++) {
        float4 v = xr[k4];
        const float* w0 = &W0s[(k4 * 4) * HID];
        const float* w1 = &W1s[(k4 * 4) * HID];
#pragma unroll
        for (int h = 0; h < HID; h++) {
            acc0[h] += v.x * w0[h] + v.y * w0[HID + h] + v.z * w0[2 * HID + h] + v.w * w0[3 * HID + h];
            acc1[h] += v.x * w1[h] + v.y * w1[HID + h] + v.z * w1[2 * HID + h] + v.w * w1[3 * HID + h];
        }
    }
    float4* z0 = reinterpret_cast<float4*>(z0g + (size_t)nd * HID);
    float4* y1 = reinterpret_cast<float4*>(y1g + (size_t)nd * HID);
#pragma unroll
    for (int q = 0; q < HID / 4; q++) {
        z0[q] = make_float4(acc0[4 * q], acc0[4 * q + 1], acc0[4 * q + 2], acc0[4 * q + 3]);
        y1[q] = make_float4(acc1[4 * q], acc1[4 * q + 1], acc1[4 * q + 2], acc1[4 * q + 3]);
    }
}

// agg[dst] += norm * src_tab[src]  (16 floats per edge, scalar atomics)
__global__ void k_scatter(const int* __restrict__ ei,
                          const float* __restrict__ nrm,
                          const float* __restrict__ src_tab,
                          float* agg, int n) {
    int e = blockIdx.x * blockDim.x + threadIdx.x;
    if (e >= n) return;
    int s = ei[e], d = ei[EE + e];
    float nw = nrm[e];
    const float4* yr = reinterpret_cast<const float4*>(src_tab + (size_t)s * HID);
    float* ap = agg + (size_t)d * HID;
#pragma unroll
    for (int q = 0; q < HID / 4; q++) {
        float4 v = yr[q];
        atomicAdd(ap + 4 * q + 0, nw * v.x);
        atomicAdd(ap + 4 * q + 1, nw * v.y);
        atomicAdd(ap + 4 * q + 2, nw * v.z);
        atomicAdd(ap + 4 * q + 3, nw * v.w);
    }
}

__global__ void k_relu(const float* __restrict__ b1, const float* __restrict__ z0,
                       const float* __restrict__ agg1, float* h, int n) {
    int i = blockIdx.x * blockDim.x + threadIdx.x;
    if (i >= n) return;
    float v = z0[i] + agg1[i] + __ldg(&b1[i & (HID - 1)]);
    h[i] = fmaxf(v, 0.0f);
}

// o = h@W2[0] + agg2@W2[1] + b2 ; out = log_softmax(o)
// Warp-per-node: lane L holds classes L and L+32 (L<8). No local arrays -> zero lmem.
__global__ void __launch_bounds__(128, 1)
k_final(const float* __restrict__ W2, const float* __restrict__ b2,
        const float* __restrict__ hg, const float* __restrict__ aggg,
        float* __restrict__ out, int n) {
    __shared__ float W20s[HID * CC];
    __shared__ float W21s[HID * CC];
    __shared__ float b2s[CC];
    for (int i = threadIdx.x; i < HID * CC; i += blockDim.x) {
        W20s[i] = W2[i];
        W21s[i] = W2[HID * CC + i];
    }
    if (threadIdx.x < CC) b2s[threadIdx.x] = b2[threadIdx.x];
    __syncthreads();

    int warp = threadIdx.x >> 5;
    int lane = threadIdx.x & 31;
    int nd = blockIdx.x * 4 + warp;
    if (nd >= n) return;

    const float* hp = hg + (size_t)nd * HID;
    const float* ap = aggg + (size_t)nd * HID;

    float oa = b2s[lane];                               // class = lane
    float ob = (lane < CC - 32) ? b2s[32 + lane] : 0.f; // class = lane+32
#pragma unroll
    for (int f = 0; f < HID; f++) {
        float hf = hp[f];   // warp-uniform load (broadcast)
        float af = ap[f];
        oa += hf * W20s[f * CC + lane] + af * W21s[f * CC + lane];
        if (lane < CC - 32)
            ob += hf * W20s[f * CC + 32 + lane] + af * W21s[f * CC + 32 + lane];
    }

    float m = (lane < CC - 32) ? fmaxf(oa, ob) : oa;
#pragma unroll
    for (int off = 16; off > 0; off >>= 1)
        m = fmaxf(m, __shfl_xor_sync(0xffffffffu, m, off));

    float s = expf(oa - m) + ((lane < CC - 32) ? expf(ob - m) : 0.0f);
#pragma unroll
    for (int off = 16; off > 0; off >>= 1)
        s += __shfl_xor_sync(0xffffffffu, s, off);

    float lse = logf(s) + m;

    float* op = out + (size_t)nd * CC;
    op[lane] = oa - lse;
    if (lane < CC - 32) op[32 + lane] = ob - lse;
}

// ---------------- prewarm: force ALL lazy driver allocations pre-checkpoint ----
// Also resolves __device__ symbol addresses into host statics so kernel args
// never rely on host-side shadows of device symbols.
namespace {
struct Prewarm {
    Prewarm() {
        void* p;
        cudaGetSymbolAddress(&p, d_deg);  p_deg  = (float*)p;
        cudaGetSymbolAddress(&p, d_dinv); p_dinv = (float*)p;
        cudaGetSymbolAddress(&p, d_norm); p_norm = (float*)p;
        cudaGetSymbolAddress(&p, d_z0);   p_z0   = (float*)p;
        cudaGetSymbolAddress(&p, d_y1);   p_y1   = (float*)p;
        cudaGetSymbolAddress(&p, d_agg1); p_agg1 = (float*)p;
        cudaGetSymbolAddress(&p, d_h);    p_h    = (float*)p;
        cudaGetSymbolAddress(&p, d_agg2); p_agg2 = (float*)p;

        // Degenerate launches (n=0) to force module/code load + lmem pool
        // sizing before the harness checkpoint. All pointers valid device
        // pointers into our scratch; weight reads (<=2048 floats) stay in
        // bounds of d_z0 (1.6M floats).
        const int*   di = (const int*)p_deg;
        const float* df = (const float*)p_z0;
        k_zero<<<1, 32>>>(p_deg, p_agg1, p_agg2, 0);
        k_deg<<<1, 32>>>(di, df, p_deg, 0);
        k_dinv<<<1, 32>>>(p_deg, p_dinv, 0);
        k_norm<<<1, 32>>>(di, df, p_dinv, p_norm, 0);
        k_gemm1<<<1, 128>>>(df, df, p_z0, p_y1, 0);
        k_scatter<<<1, 32>>>(di, p_norm, df, p_agg1, 0);
        k_relu<<<1, 32>>>(df, p_z0, p_agg1, p_h, 0);
        k_final<<<1, 128>>>(df, df, p_h, p_agg2, p_z0, 0);
        cudaDeviceSynchronize();
    }
};
Prewarm g_prewarm;
}  // namespace

// ---------------- launch ----------------
extern "C" void kernel_launch(void* const* d_in, const int* in_sizes, int n_in,
                              void* d_out, int out_size) {
    const float* x  = (const float*)d_in[0];
    const float* w  = (const float*)d_in[1];
    const float* W1 = (const float*)d_in[2];
    const float* b1 = (const float*)d_in[3];
    const float* W2 = (const float*)d_in[4];
    const float* b2 = (const float*)d_in[5];
    const int*   ei = (const int*)d_in[6];
    float* out = (float*)d_out;

    const int T = 256;
    k_zero<<<(NN * HID + T - 1) / T, T>>>(p_deg, p_agg1, p_agg2, NN * HID);
    k_deg<<<(EE + T - 1) / T, T>>>(ei, w, p_deg, EE);
    k_dinv<<<(NN + T - 1) / T, T>>>(p_deg, p_dinv, NN);
    k_norm<<<(EE + T - 1) / T, T>>>(ei, w, p_dinv, p_norm, EE);
    k_gemm1<<<(NN + 127) / 128, 128>>>(x, W1, p_z0, p_y1, NN);
    k_scatter<<<(EE + T - 1) / T, T>>>(ei, p_norm, p_y1, p_agg1, EE);
    k_relu<<<(NN * HID + T - 1) / T, T>>>(b1, p_z0, p_agg1, p_h, NN * HID);
    k_scatter<<<(EE + T - 1) / T, T>>>(ei, p_norm, p_h, p_agg2, EE);
    k_final<<<(NN + 3) / 4, 128>>>(W2, b2, p_h, p_agg2, out, NN);
}

// round 5
// speedup vs baseline: 1.2217x; 1.2217x over previous
#include <cuda_runtime.h>
#include <cuda_bf16.h>
#include <math.h>

#define NN 100000
#define EE 1600000
#define FIN 64
#define HID 16
#define CC 40

// ---------------- scratch (static device globals; no allocation) ----------------
__device__ float d_deg[NN];                 // weighted in-degree (at dst)
__device__ float d_dinv[NN];                // rsqrt(deg)
__device__ int   d_cnt[NN];                 // integer in-degree (histogram)
__device__ int   d_base[NN + 1];            // CSR row offsets (exclusive scan)
__device__ int   d_cursor[NN];              // bucket write cursors
__device__ unsigned long long d_pack[EE];   // per-edge packed (src:int32, norm:f32)
__device__ float d_z0[NN * HID];            // x @ W1[0]
__device__ float d_y1[NN * HID];            // x @ W1[1]
__device__ float d_h[NN * HID];             // relu(z0 + agg1 + b1)

// Host-side resolved device pointers (filled in prewarm ctor, pre-checkpoint).
static float* p_deg;
static float* p_dinv;
static int*   p_cnt;
static int*   p_base;
static int*   p_cursor;
static unsigned long long* p_pack;
static float* p_z0;
static float* p_y1;
static float* p_h;

// ---------------- kernels ----------------
__global__ void k_zero(float* deg, int* cnt, int n) {
    int i = blockIdx.x * blockDim.x + threadIdx.x;
    if (i >= n) return;
    deg[i] = 0.0f;
    cnt[i] = 0;
}

__global__ void k_deg(const int* __restrict__ ei, const float* __restrict__ w,
                      float* deg, int* cnt, int n) {
    int e = blockIdx.x * blockDim.x + threadIdx.x;
    if (e >= n) return;
    int d = ei[EE + e];          // dst = row 1
    atomicAdd(&deg[d], w[e]);
    atomicAdd(&cnt[d], 1);
}

__global__ void k_dinv(const float* __restrict__ deg, float* dinv, int n) {
    int i = blockIdx.x * blockDim.x + threadIdx.x;
    if (i >= n) return;
    float dg = deg[i];
    dinv[i] = (dg > 0.0f) ? rsqrtf(dg) : 0.0f;
}

// Single-block exclusive scan of cnt -> base[0..NN], base[NN]=EE; cursor=base copy.
__global__ void __launch_bounds__(1024, 1)
k_scan(const int* __restrict__ cnt, int* base, int* cursor) {
    const int T = 1024;
    int tid = threadIdx.x;
    const int per = (NN + T - 1) / T;  // 98
    int start = tid * per;
    int end = start + per; if (end > NN) end = NN;
    if (start > NN) start = NN;

    int sum = 0;
    for (int i = start; i < end; i++) sum += cnt[i];

    int lane = tid & 31, wid = tid >> 5;
    __shared__ int wsum[32];
    int v = sum;
#pragma unroll
    for (int off = 1; off < 32; off <<= 1) {
        int t = __shfl_up_sync(0xffffffffu, v, off);
        if (lane >= off) v += t;
    }
    if (lane == 31) wsum[wid] = v;
    __syncthreads();
    if (wid == 0) {
        int wv = wsum[lane];
#pragma unroll
        for (int off = 1; off < 32; off <<= 1) {
            int t = __shfl_up_sync(0xffffffffu, wv, off);
            if (lane >= off) wv += t;
        }
        wsum[lane] = wv;
    }
    __syncthreads();
    int run = v - sum + (wid > 0 ? wsum[wid - 1] : 0);  // exclusive prefix
    for (int i = start; i < end; i++) {
        base[i] = run;
        cursor[i] = run;
        run += cnt[i];
    }
    if (start < NN && end == NN) base[NN] = run;
}

// Bucket edges by dst; store (src, norm) packed in 8 bytes.
__global__ void k_bucket(const int* __restrict__ ei, const float* __restrict__ w,
                         const float* __restrict__ dinv, int* cursor,
                         unsigned long long* pack, int n) {
    int e = blockIdx.x * blockDim.x + threadIdx.x;
    if (e >= n) return;
    int s = ei[e], d = ei[EE + e];
    float nw = -dinv[s] * w[e] * dinv[d];   // lambda_max=2, loop weight=0
    int pos = atomicAdd(&cursor[d], 1);
    pack[pos] = (unsigned long long)(unsigned)s |
                ((unsigned long long)__float_as_uint(nw) << 32);
}

// z0 = x@W1[0], y1 = x@W1[1], fused (reads x once)
__global__ void __launch_bounds__(128, 1)
k_gemm1(const float* __restrict__ x, const float* __restrict__ W1,
        float* z0g, float* y1g, int n) {
    __shared__ float W0s[FIN * HID];
    __shared__ float W1s[FIN * HID];
    for (int i = threadIdx.x; i < FIN * HID; i += blockDim.x) {
        W0s[i] = W1[i];
        W1s[i] = W1[FIN * HID + i];
    }
    __syncthreads();
    int nd = blockIdx.x * blockDim.x + threadIdx.x;
    if (nd >= n) return;

    float acc0[HID], acc1[HID];
#pragma unroll
    for (int h = 0; h < HID; h++) { acc0[h] = 0.0f; acc1[h] = 0.0f; }

    const float4* xr = reinterpret_cast<const float4*>(x + (size_t)nd * FIN);
#pragma unroll
    for (int k4 = 0; k4 < FIN / 4; k4++) {
        float4 v = xr[k4];
        const float* w0 = &W0s[(k4 * 4) * HID];
        const float* w1 = &W1s[(k4 * 4) * HID];
#pragma unroll
        for (int h = 0; h < HID; h++) {
            acc0[h] += v.x * w0[h] + v.y * w0[HID + h] + v.z * w0[2 * HID + h] + v.w * w0[3 * HID + h];
            acc1[h] += v.x * w1[h] + v.y * w1[HID + h] + v.z * w1[2 * HID + h] + v.w * w1[3 * HID + h];
        }
    }
    float4* z0 = reinterpret_cast<float4*>(z0g + (size_t)nd * HID);
    float4* y1 = reinterpret_cast<float4*>(y1g + (size_t)nd * HID);
#pragma unroll
    for (int q = 0; q < HID / 4; q++) {
        z0[q] = make_float4(acc0[4 * q], acc0[4 * q + 1], acc0[4 * q + 2], acc0[4 * q + 3]);
        y1[q] = make_float4(acc1[4 * q], acc1[4 * q + 1], acc1[4 * q + 2], acc1[4 * q + 3]);
    }
}

// Gather layer 1: warp per node. Lanes split into two groups of 16 (g=lane>>4),
// each group walks alternate in-edges; lane's feature f=lane&15.
// h[nd][f] = relu(z0[nd][f] + sum_j nw_j * y1[src_j][f] + b1[f])
__global__ void __launch_bounds__(256, 8)
k_gather1(const int* __restrict__ base, const unsigned long long* __restrict__ pack,
          const float* __restrict__ y1, const float* __restrict__ z0,
          const float* __restrict__ b1, float* __restrict__ h, int n) {
    int warp = threadIdx.x >> 5;
    int lane = threadIdx.x & 31;
    int nd = blockIdx.x * 8 + warp;
    if (nd >= n) return;

    int s = base[nd], e = base[nd + 1];
    int g = lane >> 4, f = lane & 15;

    float acc = 0.0f;
    for (int j = s + g; j < e; j += 2) {
        unsigned long long p = pack[j];
        int src = (int)(unsigned)(p & 0xffffffffULL);
        float nw = __uint_as_float((unsigned)(p >> 32));
        acc += nw * y1[(size_t)src * HID + f];
    }
    acc += __shfl_xor_sync(0xffffffffu, acc, 16);

    if (g == 0) {
        float v = z0[(size_t)nd * HID + f] + acc + __ldg(&b1[f]);
        h[(size_t)nd * HID + f] = fmaxf(v, 0.0f);
    }
}

// Gather layer 2 fused with final GEMM + log_softmax.
// Warp per node: gather agg2 (16 feats), then lane L computes classes L and L+32.
__global__ void __launch_bounds__(256, 8)
k_gather2_final(const int* __restrict__ base, const unsigned long long* __restrict__ pack,
                const float* __restrict__ h, const float* __restrict__ W2,
                const float* __restrict__ b2, float* __restrict__ out, int n) {
    __shared__ float W20s[HID * CC];
    __shared__ float W21s[HID * CC];
    __shared__ float b2s[CC];
    __shared__ float aggs[8][HID];
    for (int i = threadIdx.x; i < HID * CC; i += blockDim.x) {
        W20s[i] = W2[i];
        W21s[i] = W2[HID * CC + i];
    }
    if (threadIdx.x < CC) b2s[threadIdx.x] = b2[threadIdx.x];
    __syncthreads();

    int warp = threadIdx.x >> 5;
    int lane = threadIdx.x & 31;
    int nd = blockIdx.x * 8 + warp;
    if (nd >= n) return;

    int s = base[nd], e = base[nd + 1];
    int g = lane >> 4, f = lane & 15;

    float acc = 0.0f;
    for (int j = s + g; j < e; j += 2) {
        unsigned long long p = pack[j];
        int src = (int)(unsigned)(p & 0xffffffffULL);
        float nw = __uint_as_float((unsigned)(p >> 32));
        acc += nw * h[(size_t)src * HID + f];
    }
    acc += __shfl_xor_sync(0xffffffffu, acc, 16);
    if (g == 0) aggs[warp][f] = acc;
    __syncwarp();

    const float* hp = h + (size_t)nd * HID;
    float oa = b2s[lane];                               // class = lane
    float ob = (lane < CC - 32) ? b2s[32 + lane] : 0.f; // class = lane+32
#pragma unroll
    for (int ff = 0; ff < HID; ff++) {
        float hf = hp[ff];           // warp-uniform broadcast load
        float af = aggs[warp][ff];
        oa += hf * W20s[ff * CC + lane] + af * W21s[ff * CC + lane];
        if (lane < CC - 32)
            ob += hf * W20s[ff * CC + 32 + lane] + af * W21s[ff * CC + 32 + lane];
    }

    float m = (lane < CC - 32) ? fmaxf(oa, ob) : oa;
#pragma unroll
    for (int off = 16; off > 0; off >>= 1)
        m = fmaxf(m, __shfl_xor_sync(0xffffffffu, m, off));

    float sexp = expf(oa - m) + ((lane < CC - 32) ? expf(ob - m) : 0.0f);
#pragma unroll
    for (int off = 16; off > 0; off >>= 1)
        sexp += __shfl_xor_sync(0xffffffffu, sexp, off);

    float lse = logf(sexp) + m;

    float* op = out + (size_t)nd * CC;
    op[lane] = oa - lse;
    if (lane < CC - 32) op[32 + lane] = ob - lse;
}

// ---------------- prewarm: force ALL lazy driver allocations pre-checkpoint ----
namespace {
struct Prewarm {
    Prewarm() {
        void* p;
        cudaGetSymbolAddress(&p, d_deg);    p_deg    = (float*)p;
        cudaGetSymbolAddress(&p, d_dinv);   p_dinv   = (float*)p;
        cudaGetSymbolAddress(&p, d_cnt);    p_cnt    = (int*)p;
        cudaGetSymbolAddress(&p, d_base);   p_base   = (int*)p;
        cudaGetSymbolAddress(&p, d_cursor); p_cursor = (int*)p;
        cudaGetSymbolAddress(&p, d_pack);   p_pack   = (unsigned long long*)p;
        cudaGetSymbolAddress(&p, d_z0);     p_z0     = (float*)p;
        cudaGetSymbolAddress(&p, d_y1);     p_y1     = (float*)p;
        cudaGetSymbolAddress(&p, d_h);      p_h      = (float*)p;

        // Degenerate launches (n=0 where applicable) to force module/code load
        // + lmem pool sizing before the harness checkpoint. k_scan does real
        // (harmless) work on scratch garbage. All pointers in-bounds.
        const int*   di = (const int*)p_cnt;
        const float* df = (const float*)p_z0;
        k_zero<<<1, 32>>>(p_deg, p_cnt, 0);
        k_deg<<<1, 32>>>(di, df, p_deg, p_cnt, 0);
        k_dinv<<<1, 32>>>(p_deg, p_dinv, 0);
        k_scan<<<1, 1024>>>(p_cnt, p_base, p_cursor);
        k_bucket<<<1, 32>>>(di, df, p_dinv, p_cursor, p_pack, 0);
        k_gemm1<<<1, 128>>>(df, df, p_z0, p_y1, 0);
        k_gather1<<<1, 256>>>(p_base, p_pack, p_y1, p_z0, df, p_h, 0);
        k_gather2_final<<<1, 256>>>(p_base, p_pack, p_h, df, df, p_z0, 0);
        cudaDeviceSynchronize();
    }
};
Prewarm g_prewarm;
}  // namespace

// ---------------- launch ----------------
extern "C" void kernel_launch(void* const* d_in, const int* in_sizes, int n_in,
                              void* d_out, int out_size) {
    const float* x  = (const float*)d_in[0];
    const float* w  = (const float*)d_in[1];
    const float* W1 = (const float*)d_in[2];
    const float* b1 = (const float*)d_in[3];
    const float* W2 = (const float*)d_in[4];
    const float* b2 = (const float*)d_in[5];
    const int*   ei = (const int*)d_in[6];
    float* out = (float*)d_out;

    const int T = 256;
    k_zero<<<(NN + T - 1) / T, T>>>(p_deg, p_cnt, NN);
    k_deg<<<(EE + T - 1) / T, T>>>(ei, w, p_deg, p_cnt, EE);
    k_dinv<<<(NN + T - 1) / T, T>>>(p_deg, p_dinv, NN);
    k_scan<<<1, 1024>>>(p_cnt, p_base, p_cursor);
    k_bucket<<<(EE + T - 1) / T, T>>>(ei, w, p_dinv, p_cursor, p_pack, EE);
    k_gemm1<<<(NN + 127) / 128, 128>>>(x, W1, p_z0, p_y1, NN);
    k_gather1<<<(NN + 7) / 8, 256>>>(p_base, p_pack, p_y1, p_z0, b1, p_h, NN);
    k_gather2_final<<<(NN + 7) / 8, 256>>>(p_base, p_pack, p_h, W2, b2, out, NN);
}